// round 3
// baseline (speedup 1.0000x reference)
#include <cuda_runtime.h>
#include <math.h>

// ---------------- problem constants ----------------
constexpr int N_NODES = 200000;
constexpr int N_EDGES = 4000000;
constexpr int N_W2B   = 2000000;

// ---------------- device scratch (static; no runtime allocs) ----------------
__device__ __align__(16) float g_dinv[N_NODES];
__device__ __align__(16) float g_norm[N_EDGES];
__device__ __align__(16) float g_xw  [N_NODES * 32];
__device__ __align__(16) float g_bufA[N_NODES * 32];
__device__ __align__(16) float g_bufB[N_NODES * 32];

__device__ __forceinline__ float sigmoidf_(float x) {
    return 1.0f / (1.0f + expf(-x));
}

// ---------------- stage 0: degree / dinv / norm ----------------
__global__ void zero_deg_kernel(float* deg) {
    int i = blockIdx.x * blockDim.x + threadIdx.x;
    if (i < N_NODES) deg[i] = 0.0f;
}

__global__ void deg_scatter_kernel(const int* __restrict__ dst,
                                   const float* __restrict__ ew,
                                   float* deg) {
    int e = blockIdx.x * blockDim.x + threadIdx.x;
    if (e < N_EDGES) {
        float w = sigmoidf_(ew[e]);
        atomicAdd(deg + dst[e], w);
    }
}

__global__ void finalize_dinv_kernel(float* dinv) {
    int i = blockIdx.x * blockDim.x + threadIdx.x;
    if (i < N_NODES) {
        // self-loop adds weight 1 -> deg+1 >= 1 > 0 always
        dinv[i] = rsqrtf(dinv[i] + 1.0f);
    }
}

__global__ void prep_edges_kernel(const int* __restrict__ src,
                                  const int* __restrict__ dst,
                                  const float* __restrict__ ew,
                                  const float* __restrict__ dinv,
                                  float* __restrict__ normO) {
    int e = blockIdx.x * blockDim.x + threadIdx.x;
    if (e < N_EDGES) {
        normO[e] = dinv[src[e]] * sigmoidf_(ew[e]) * dinv[dst[e]];
    }
}

// ---------------- fused GEMM + self-loop + bias init ----------------
template <int IN, int OUT, bool RELU_IN>
__global__ void gemm_init_kernel(const float* __restrict__ h,
                                 const float* __restrict__ W,
                                 const float* __restrict__ b,
                                 const float* __restrict__ dinv,
                                 float* __restrict__ xw,
                                 float* __restrict__ acc) {
    __shared__ float sW[IN * OUT];
    __shared__ float sb[OUT];
    for (int t = threadIdx.x; t < IN * OUT; t += blockDim.x) sW[t] = W[t];
    for (int t = threadIdx.x; t < OUT; t += blockDim.x) sb[t] = b[t];
    __syncthreads();

    int i = blockIdx.x * blockDim.x + threadIdx.x;
    if (i >= N_NODES) return;

    float in[IN];
#pragma unroll
    for (int k = 0; k < IN; k++) {
        float v = h[(size_t)i * IN + k];
        in[k] = RELU_IN ? fmaxf(v, 0.0f) : v;
    }
    float di = dinv[i];
    float sn = di * di;  // self-loop norm (weight 1)

#pragma unroll
    for (int o = 0; o < OUT; o++) {
        float v = 0.0f;
#pragma unroll
        for (int k = 0; k < IN; k++) v += in[k] * sW[k * OUT + o];
        xw[(size_t)i * OUT + o] = v;
        acc[(size_t)i * OUT + o] = v * sn + sb[o];
    }
}

// ---------------- edge scatter: acc[dst] += xw[src] * norm ----------------
template <int OUT>
__global__ void scatter_kernel(const int* __restrict__ src,
                               const int* __restrict__ dst,
                               const float* __restrict__ norm,
                               const float* __restrict__ xw,
                               float* acc) {
    int e = blockIdx.x * blockDim.x + threadIdx.x;
    if (e >= N_EDGES) return;
    int s = src[e];
    int d = dst[e];
    float nm = norm[e];
    const float4* xs = (const float4*)(xw + (size_t)s * OUT);
    float* ac = acc + (size_t)d * OUT;
#pragma unroll
    for (int j = 0; j < OUT / 4; j++) {
        float4 v = xs[j];
        atomicAdd(ac + 4 * j + 0, v.x * nm);
        atomicAdd(ac + 4 * j + 1, v.y * nm);
        atomicAdd(ac + 4 * j + 2, v.z * nm);
        atomicAdd(ac + 4 * j + 3, v.w * nm);
    }
}

// ---------------- final edge MLP ----------------
__global__ void edge_mlp_kernel(const int* __restrict__ w2b,
                                const float* __restrict__ Wl1,
                                const float* __restrict__ bl1,
                                const float* __restrict__ Wl2,
                                const float* __restrict__ bl2,
                                const float* __restrict__ hfin,
                                float* __restrict__ out) {
    __shared__ float sW1[64 * 4];
    __shared__ float sb1[4];
    __shared__ float sW2[4 * 3];
    __shared__ float sb2[3];
    for (int t = threadIdx.x; t < 64 * 4; t += blockDim.x) sW1[t] = Wl1[t];
    if (threadIdx.x < 4)  sb1[threadIdx.x] = bl1[threadIdx.x];
    if (threadIdx.x < 12) sW2[threadIdx.x] = Wl2[threadIdx.x];
    if (threadIdx.x < 3)  sb2[threadIdx.x] = bl2[threadIdx.x];
    __syncthreads();

    int e = blockIdx.x * blockDim.x + threadIdx.x;
    if (e >= N_W2B) return;

    int a = w2b[e];
    int b = w2b[e + N_W2B];
    const float* ha = hfin + (size_t)a * 32;
    const float* hb = hfin + (size_t)b * 32;

    float hid[4] = {sb1[0], sb1[1], sb1[2], sb1[3]};
#pragma unroll
    for (int k = 0; k < 32; k++) {
        float v = fmaxf(ha[k], 0.0f);
#pragma unroll
        for (int j = 0; j < 4; j++) hid[j] += v * sW1[k * 4 + j];
    }
#pragma unroll
    for (int k = 0; k < 32; k++) {
        float v = fmaxf(hb[k], 0.0f);
#pragma unroll
        for (int j = 0; j < 4; j++) hid[j] += v * sW1[(32 + k) * 4 + j];
    }
#pragma unroll
    for (int c = 0; c < 3; c++) {
        float o = sb2[c];
#pragma unroll
        for (int j = 0; j < 4; j++) o += hid[j] * sW2[j * 3 + c];
        out[(size_t)e * 3 + c] = o;
    }
}

// ---------------- launch ----------------
extern "C" void kernel_launch(void* const* d_in, const int* in_sizes, int n_in,
                              void* d_out, int out_size) {
    const float* x    = (const float*)d_in[0];
    const int*   eidx = (const int*)d_in[1];   // int32 (JAX default: x64 disabled)
    const int*   w2b  = (const int*)d_in[2];   // int32
    const float* ew   = (const float*)d_in[3];
    const float *W1 = (const float*)d_in[4],  *b1 = (const float*)d_in[5];
    const float *W2 = (const float*)d_in[6],  *b2 = (const float*)d_in[7];
    const float *W3 = (const float*)d_in[8],  *b3 = (const float*)d_in[9];
    const float *Wl1 = (const float*)d_in[10], *bl1 = (const float*)d_in[11];
    const float *Wl2 = (const float*)d_in[12], *bl2 = (const float*)d_in[13];
    float* out = (float*)d_out;

    // Resolve scratch symbols host-side; pass plain global pointers to kernels.
    float *dinv, *normp, *xw, *bufA, *bufB;
    cudaGetSymbolAddress((void**)&dinv,  g_dinv);
    cudaGetSymbolAddress((void**)&normp, g_norm);
    cudaGetSymbolAddress((void**)&xw,    g_xw);
    cudaGetSymbolAddress((void**)&bufA,  g_bufA);
    cudaGetSymbolAddress((void**)&bufB,  g_bufB);

    const int* src = eidx;
    const int* dst = eidx + N_EDGES;

    const int T = 256;
    const int nb_nodes = (N_NODES + T - 1) / T;
    const int nb_edges = (N_EDGES + T - 1) / T;
    const int nb_w2b   = (N_W2B + T - 1) / T;

    // stage 0: degree, dinv, per-edge norm
    zero_deg_kernel<<<nb_nodes, T>>>(dinv);
    deg_scatter_kernel<<<nb_edges, T>>>(dst, ew, dinv);
    finalize_dinv_kernel<<<nb_nodes, T>>>(dinv);
    prep_edges_kernel<<<nb_edges, T>>>(src, dst, ew, dinv, normp);

    // layer 1: x(7) -> bufA(8)
    gemm_init_kernel<7, 8, false><<<nb_nodes, T>>>(x, W1, b1, dinv, xw, bufA);
    scatter_kernel<8><<<nb_edges, T>>>(src, dst, normp, xw, bufA);

    // layer 2: relu(bufA)(8) -> bufB(16)
    gemm_init_kernel<8, 16, true><<<nb_nodes, T>>>(bufA, W2, b2, dinv, xw, bufB);
    scatter_kernel<16><<<nb_edges, T>>>(src, dst, normp, xw, bufB);

    // layer 3: relu(bufB)(16) -> bufA(32)
    gemm_init_kernel<16, 32, true><<<nb_nodes, T>>>(bufB, W3, b3, dinv, xw, bufA);
    scatter_kernel<32><<<nb_edges, T>>>(src, dst, normp, xw, bufA);

    // edge MLP on relu(bufA)
    edge_mlp_kernel<<<nb_w2b, T>>>(w2b, Wl1, bl1, Wl2, bl2, bufA, out);
}

// round 4
// speedup vs baseline: 3.9244x; 3.9244x over previous
#include <cuda_runtime.h>
#include <math.h>

// ---------------- problem constants ----------------
constexpr int N_NODES = 200000;
constexpr int N_EDGES = 4000000;
constexpr int N_W2B   = 2000000;
constexpr int SCAN_B  = 1024;
constexpr int N_SCANBLK = (N_NODES + SCAN_B - 1) / SCAN_B;   // 196

// ---------------- device scratch (static; no runtime allocs) ----------------
__device__ __align__(16) float g_dinv[N_NODES];
__device__ __align__(16) int   g_cnt [N_NODES];
__device__ __align__(16) int   g_rowptr[N_NODES + 1];
__device__ __align__(16) int   g_cursor[N_NODES];
__device__ __align__(16) int   g_bsums[N_SCANBLK];
__device__ __align__(16) float g_sigew[N_EDGES];
__device__ __align__(16) int   g_csrc [N_EDGES];
__device__ __align__(16) float g_cnorm[N_EDGES];
__device__ __align__(16) float g_xw  [N_NODES * 32];
__device__ __align__(16) float g_bufA[N_NODES * 32];
__device__ __align__(16) float g_bufB[N_NODES * 32];
__device__ __align__(16) float4 g_pa[N_NODES];
__device__ __align__(16) float4 g_pb[N_NODES];

__device__ __forceinline__ float sigmoidf_(float x) {
    return 1.0f / (1.0f + expf(-x));
}

// ---------------- stage 0: degree + histogram ----------------
__global__ void zero_kernel(float* deg, int* cnt) {
    int i = blockIdx.x * blockDim.x + threadIdx.x;
    if (i < N_NODES) { deg[i] = 0.0f; cnt[i] = 0; }
}

__global__ void pass1_kernel(const int* __restrict__ dst,
                             const float* __restrict__ ew,
                             float* __restrict__ sigew,
                             float* deg, int* cnt) {
    int e = blockIdx.x * blockDim.x + threadIdx.x;
    if (e < N_EDGES) {
        float sg = sigmoidf_(ew[e]);
        sigew[e] = sg;
        int d = dst[e];
        atomicAdd(deg + d, sg);
        atomicAdd(cnt + d, 1);
    }
}

__global__ void finalize_dinv_kernel(float* dinv) {
    int i = blockIdx.x * blockDim.x + threadIdx.x;
    if (i < N_NODES) dinv[i] = rsqrtf(dinv[i] + 1.0f);  // +1: self-loop
}

// ---------------- exclusive scan of cnt -> rowptr ----------------
__global__ void scan_block_kernel(const int* __restrict__ cnt,
                                  int* __restrict__ excl,
                                  int* __restrict__ bsums) {
    __shared__ int sh[SCAN_B];
    int t = threadIdx.x;
    int gid = blockIdx.x * SCAN_B + t;
    int v = (gid < N_NODES) ? cnt[gid] : 0;
    sh[t] = v;
    __syncthreads();
#pragma unroll
    for (int off = 1; off < SCAN_B; off <<= 1) {
        int add = (t >= off) ? sh[t - off] : 0;
        __syncthreads();
        sh[t] += add;
        __syncthreads();
    }
    if (gid < N_NODES) excl[gid] = sh[t] - v;            // exclusive
    if (t == SCAN_B - 1) bsums[blockIdx.x] = sh[t];      // block total
}

__global__ void scan_bsums_kernel(int* bsums) {
    __shared__ int sh[N_SCANBLK];
    int t = threadIdx.x;
    if (t < N_SCANBLK) sh[t] = bsums[t];
    __syncthreads();
    if (t == 0) {
        int run = 0;
        for (int i = 0; i < N_SCANBLK; i++) { int c = sh[i]; sh[i] = run; run += c; }
    }
    __syncthreads();
    if (t < N_SCANBLK) bsums[t] = sh[t];
}

__global__ void scan_add_kernel(int* __restrict__ rowptr,
                                int* __restrict__ cursor,
                                const int* __restrict__ bsums) {
    int gid = blockIdx.x * SCAN_B + threadIdx.x;
    if (gid < N_NODES) {
        int v = rowptr[gid] + bsums[blockIdx.x];
        rowptr[gid] = v;
        cursor[gid] = v;
        if (gid == 0) rowptr[N_NODES] = N_EDGES;
    }
}

// ---------------- CSR fill ----------------
__global__ void fill_kernel(const int* __restrict__ src,
                            const int* __restrict__ dst,
                            const float* __restrict__ sigew,
                            const float* __restrict__ dinv,
                            int* cursor,
                            int* __restrict__ csrc,
                            float* __restrict__ cnorm) {
    int e = blockIdx.x * blockDim.x + threadIdx.x;
    if (e >= N_EDGES) return;
    int s = src[e], d = dst[e];
    int pos = atomicAdd(cursor + d, 1);
    csrc[pos] = s;
    cnorm[pos] = dinv[s] * sigew[e] * dinv[d];
}

// ---------------- per-layer: xw = (relu?)h @ W ----------------
template <int IN, int OUT, bool RELU_IN>
__global__ void gemm_kernel(const float* __restrict__ h,
                            const float* __restrict__ W,
                            float* __restrict__ xw) {
    __shared__ float sW[IN * OUT];
    for (int t = threadIdx.x; t < IN * OUT; t += blockDim.x) sW[t] = W[t];
    __syncthreads();
    int i = blockIdx.x * blockDim.x + threadIdx.x;
    if (i >= N_NODES) return;
    float in[IN];
#pragma unroll
    for (int k = 0; k < IN; k++) {
        float v = h[(size_t)i * IN + k];
        in[k] = RELU_IN ? fmaxf(v, 0.0f) : v;
    }
#pragma unroll
    for (int o = 0; o < OUT; o++) {
        float v = 0.0f;
#pragma unroll
        for (int k = 0; k < IN; k++) v += in[k] * sW[k * OUT + o];
        xw[(size_t)i * OUT + o] = v;
    }
}

// ---------------- per-layer gather: out[n] = b + xw[n]*dinv^2 + sum_e xw[src]*norm
// one warp per node; lane = rep*OUT + j (REP = 32/OUT edge slices)
template <int OUT>
__global__ void gather_kernel(const int* __restrict__ rowptr,
                              const int* __restrict__ csrc,
                              const float* __restrict__ cnorm,
                              const float* __restrict__ xw,
                              const float* __restrict__ dinv,
                              const float* __restrict__ b,
                              float* __restrict__ outh) {
    constexpr int REP = 32 / OUT;
    int warp = (blockIdx.x * blockDim.x + threadIdx.x) >> 5;
    if (warp >= N_NODES) return;
    int lane = threadIdx.x & 31;
    int rep  = lane / OUT;
    int j    = lane % OUT;

    int start = rowptr[warp];
    int end   = rowptr[warp + 1];

    float s = 0.0f;
    for (int e = start + rep; e < end; e += REP) {
        int   sidx = csrc[e];
        float nm   = cnorm[e];
        s += xw[(size_t)sidx * OUT + j] * nm;
    }
#pragma unroll
    for (int off = OUT; off < 32; off <<= 1)
        s += __shfl_xor_sync(0xffffffffu, s, off);

    if (rep == 0) {
        float di = dinv[warp];
        float self = xw[(size_t)warp * OUT + j] * di * di;
        outh[(size_t)warp * OUT + j] = s + self + __ldg(b + j);
    }
}

// ---------------- node projections for edge MLP ----------------
// pa[n] = relu(h[n]) @ Wl1[0:32], pb[n] = relu(h[n]) @ Wl1[32:64]
__global__ void node_proj_kernel(const float* __restrict__ h,
                                 const float* __restrict__ Wl1,
                                 float4* __restrict__ pa,
                                 float4* __restrict__ pb) {
    __shared__ float sW[64 * 4];
    for (int t = threadIdx.x; t < 64 * 4; t += blockDim.x) sW[t] = Wl1[t];
    __syncthreads();
    int i = blockIdx.x * blockDim.x + threadIdx.x;
    if (i >= N_NODES) return;
    float va[4] = {0, 0, 0, 0}, vb[4] = {0, 0, 0, 0};
#pragma unroll
    for (int k = 0; k < 32; k++) {
        float v = fmaxf(h[(size_t)i * 32 + k], 0.0f);
#pragma unroll
        for (int j = 0; j < 4; j++) {
            va[j] += v * sW[k * 4 + j];
            vb[j] += v * sW[(32 + k) * 4 + j];
        }
    }
    pa[i] = make_float4(va[0], va[1], va[2], va[3]);
    pb[i] = make_float4(vb[0], vb[1], vb[2], vb[3]);
}

// ---------------- final edge MLP: out = (pa[a]+pb[b]+bl1) @ Wl2 + bl2 ----------------
__global__ void edge_mlp_kernel(const int* __restrict__ w2b,
                                const float* __restrict__ bl1,
                                const float* __restrict__ Wl2,
                                const float* __restrict__ bl2,
                                const float4* __restrict__ pa,
                                const float4* __restrict__ pb,
                                float* __restrict__ out) {
    __shared__ float sW2[12], sb1[4], sb2[3];
    if (threadIdx.x < 12) sW2[threadIdx.x] = Wl2[threadIdx.x];
    if (threadIdx.x < 4)  sb1[threadIdx.x] = bl1[threadIdx.x];
    if (threadIdx.x < 3)  sb2[threadIdx.x] = bl2[threadIdx.x];
    __syncthreads();

    int e = blockIdx.x * blockDim.x + threadIdx.x;
    if (e >= N_W2B) return;
    int a = w2b[e];
    int b = w2b[e + N_W2B];
    float4 va = pa[a];
    float4 vb = pb[b];
    float h0 = va.x + vb.x + sb1[0];
    float h1 = va.y + vb.y + sb1[1];
    float h2 = va.z + vb.z + sb1[2];
    float h3 = va.w + vb.w + sb1[3];
#pragma unroll
    for (int c = 0; c < 3; c++) {
        out[(size_t)e * 3 + c] =
            h0 * sW2[0 * 3 + c] + h1 * sW2[1 * 3 + c] +
            h2 * sW2[2 * 3 + c] + h3 * sW2[3 * 3 + c] + sb2[c];
    }
}

// ---------------- launch ----------------
extern "C" void kernel_launch(void* const* d_in, const int* in_sizes, int n_in,
                              void* d_out, int out_size) {
    const float* x    = (const float*)d_in[0];
    const int*   eidx = (const int*)d_in[1];
    const int*   w2b  = (const int*)d_in[2];
    const float* ew   = (const float*)d_in[3];
    const float *W1 = (const float*)d_in[4],  *b1 = (const float*)d_in[5];
    const float *W2 = (const float*)d_in[6],  *b2 = (const float*)d_in[7];
    const float *W3 = (const float*)d_in[8],  *b3 = (const float*)d_in[9];
    const float *Wl1 = (const float*)d_in[10], *bl1 = (const float*)d_in[11];
    const float *Wl2 = (const float*)d_in[12], *bl2 = (const float*)d_in[13];
    float* out = (float*)d_out;

    float *dinv, *sigew, *cnorm, *xw, *bufA, *bufB;
    int *cnt, *rowptr, *cursor, *bsums, *csrc;
    float4 *pa, *pb;
    cudaGetSymbolAddress((void**)&dinv,   g_dinv);
    cudaGetSymbolAddress((void**)&cnt,    g_cnt);
    cudaGetSymbolAddress((void**)&rowptr, g_rowptr);
    cudaGetSymbolAddress((void**)&cursor, g_cursor);
    cudaGetSymbolAddress((void**)&bsums,  g_bsums);
    cudaGetSymbolAddress((void**)&sigew,  g_sigew);
    cudaGetSymbolAddress((void**)&csrc,   g_csrc);
    cudaGetSymbolAddress((void**)&cnorm,  g_cnorm);
    cudaGetSymbolAddress((void**)&xw,     g_xw);
    cudaGetSymbolAddress((void**)&bufA,   g_bufA);
    cudaGetSymbolAddress((void**)&bufB,   g_bufB);
    cudaGetSymbolAddress((void**)&pa,     g_pa);
    cudaGetSymbolAddress((void**)&pb,     g_pb);

    const int* src = eidx;
    const int* dst = eidx + N_EDGES;

    const int T = 256;
    const int nb_nodes = (N_NODES + T - 1) / T;
    const int nb_edges = (N_EDGES + T - 1) / T;
    const int nb_w2b   = (N_W2B + T - 1) / T;
    const int nb_warp  = (N_NODES * 32 + T - 1) / T;   // one warp per node

    // stage 0: degree + histogram, dinv
    zero_kernel<<<nb_nodes, T>>>(dinv, cnt);
    pass1_kernel<<<nb_edges, T>>>(dst, ew, sigew, dinv, cnt);
    finalize_dinv_kernel<<<nb_nodes, T>>>(dinv);

    // scan cnt -> rowptr (exclusive) + cursor copy
    scan_block_kernel<<<N_SCANBLK, SCAN_B>>>(cnt, rowptr, bsums);
    scan_bsums_kernel<<<1, SCAN_B>>>(bsums);
    scan_add_kernel<<<N_SCANBLK, SCAN_B>>>(rowptr, cursor, bsums);

    // CSR fill (src + norm per slot)
    fill_kernel<<<nb_edges, T>>>(src, dst, sigew, dinv, cursor, csrc, cnorm);

    // layer 1: x(7) -> bufA(8)
    gemm_kernel<7, 8, false><<<nb_nodes, T>>>(x, W1, xw);
    gather_kernel<8><<<nb_warp, T>>>(rowptr, csrc, cnorm, xw, dinv, b1, bufA);

    // layer 2: relu(bufA)(8) -> bufB(16)
    gemm_kernel<8, 16, true><<<nb_nodes, T>>>(bufA, W2, xw);
    gather_kernel<16><<<nb_warp, T>>>(rowptr, csrc, cnorm, xw, dinv, b2, bufB);

    // layer 3: relu(bufB)(16) -> bufA(32)
    gemm_kernel<16, 32, true><<<nb_nodes, T>>>(bufB, W3, xw);
    gather_kernel<32><<<nb_warp, T>>>(rowptr, csrc, cnorm, xw, dinv, b3, bufA);

    // edge MLP: per-node projection then 2M-edge combine
    node_proj_kernel<<<nb_nodes, T>>>(bufA, Wl1, pa, pb);
    edge_mlp_kernel<<<nb_w2b, T>>>(w2b, bl1, Wl2, bl2, pa, pb, out);
}

// round 5
// speedup vs baseline: 4.5924x; 1.1702x over previous
#include <cuda_runtime.h>
#include <math.h>

// ---------------- problem constants ----------------
constexpr int N_NODES = 200000;
constexpr int N_EDGES = 4000000;
constexpr int N_W2B   = 2000000;
constexpr int SCAN_B  = 1024;
constexpr int N_SCANBLK = (N_NODES + SCAN_B - 1) / SCAN_B;   // 196

// ---------------- device scratch (static; no runtime allocs) ----------------
__device__ __align__(16) float  g_dinv[N_NODES];
__device__ __align__(16) int    g_cnt [N_NODES];
__device__ __align__(16) int    g_rowptr[N_NODES + 1];
__device__ __align__(16) int    g_cursor[N_NODES];
__device__ __align__(16) int    g_bsums[N_SCANBLK];
__device__ __align__(16) float2 g_edges[N_EDGES];          // packed (src, norm)
__device__ __align__(16) float  g_agg [N_NODES * 16];      // aggregation buffer (max IN=16)
__device__ __align__(16) float  g_h1  [N_NODES * 8];
__device__ __align__(16) float  g_h2  [N_NODES * 16];
__device__ __align__(16) float  g_h3  [N_NODES * 32];
__device__ __align__(16) float4 g_pa[N_NODES];
__device__ __align__(16) float4 g_pb[N_NODES];

__device__ __forceinline__ float sigmoidf_(float x) {
    return 1.0f / (1.0f + expf(-x));
}

// ---------------- stage 0: degree + histogram ----------------
__global__ void zero_kernel(float* deg, int* cnt) {
    int i = blockIdx.x * blockDim.x + threadIdx.x;
    if (i < N_NODES) { deg[i] = 0.0f; cnt[i] = 0; }
}

__global__ void pass1_kernel(const int* __restrict__ dst,
                             const float* __restrict__ ew,
                             float* deg, int* cnt) {
    int e = blockIdx.x * blockDim.x + threadIdx.x;
    if (e < N_EDGES) {
        int d = dst[e];
        atomicAdd(deg + d, sigmoidf_(ew[e]));
        atomicAdd(cnt + d, 1);
    }
}

__global__ void finalize_dinv_kernel(float* dinv) {
    int i = blockIdx.x * blockDim.x + threadIdx.x;
    if (i < N_NODES) dinv[i] = rsqrtf(dinv[i] + 1.0f);  // +1: self-loop
}

// ---------------- exclusive scan of cnt -> rowptr ----------------
__global__ void scan_block_kernel(const int* __restrict__ cnt,
                                  int* __restrict__ excl,
                                  int* __restrict__ bsums) {
    __shared__ int sh[SCAN_B];
    int t = threadIdx.x;
    int gid = blockIdx.x * SCAN_B + t;
    int v = (gid < N_NODES) ? cnt[gid] : 0;
    sh[t] = v;
    __syncthreads();
#pragma unroll
    for (int off = 1; off < SCAN_B; off <<= 1) {
        int add = (t >= off) ? sh[t - off] : 0;
        __syncthreads();
        sh[t] += add;
        __syncthreads();
    }
    if (gid < N_NODES) excl[gid] = sh[t] - v;            // exclusive
    if (t == SCAN_B - 1) bsums[blockIdx.x] = sh[t];      // block total
}

__global__ void scan_bsums_kernel(int* bsums) {
    __shared__ int sh[N_SCANBLK];
    int t = threadIdx.x;
    if (t < N_SCANBLK) sh[t] = bsums[t];
    __syncthreads();
    if (t == 0) {
        int run = 0;
        for (int i = 0; i < N_SCANBLK; i++) { int c = sh[i]; sh[i] = run; run += c; }
    }
    __syncthreads();
    if (t < N_SCANBLK) bsums[t] = sh[t];
}

__global__ void scan_add_kernel(int* __restrict__ rowptr,
                                int* __restrict__ cursor,
                                const int* __restrict__ bsums) {
    int gid = blockIdx.x * SCAN_B + threadIdx.x;
    if (gid < N_NODES) {
        int v = rowptr[gid] + bsums[blockIdx.x];
        rowptr[gid] = v;
        cursor[gid] = v;
        if (gid == 0) rowptr[N_NODES] = N_EDGES;
    }
}

// ---------------- CSR fill: one packed 8B record per edge ----------------
__global__ void fill_kernel(const int* __restrict__ src,
                            const int* __restrict__ dst,
                            const float* __restrict__ ew,
                            const float* __restrict__ dinv,
                            int* cursor,
                            float2* __restrict__ edges) {
    int e = blockIdx.x * blockDim.x + threadIdx.x;
    if (e >= N_EDGES) return;
    int s = src[e], d = dst[e];
    int pos = atomicAdd(cursor + d, 1);
    float nm = dinv[s] * sigmoidf_(ew[e]) * dinv[d];
    edges[pos] = make_float2(__int_as_float(s), nm);
}

// ---------------- aggregate: agg[n] = dinv^2*h[n] + sum_e norm*h[src]  (dim = DIM)
// one warp per node; lane = rep*DIM + j
template <int DIM>
__global__ void aggregate_kernel(const int* __restrict__ rowptr,
                                 const float2* __restrict__ edges,
                                 const float* __restrict__ h,
                                 const float* __restrict__ dinv,
                                 float* __restrict__ agg) {
    constexpr int REP = 32 / DIM;                 // 7->4, 8->4, 16->2
    int warp = (blockIdx.x * blockDim.x + threadIdx.x) >> 5;
    if (warp >= N_NODES) return;
    int lane = threadIdx.x & 31;
    int rep  = lane / DIM;
    int j    = lane - rep * DIM;
    bool active = rep < REP;

    int start = rowptr[warp];
    int end   = rowptr[warp + 1];

    float s = 0.0f;
    if (active) {
        for (int e = start + rep; e < end; e += REP) {
            float2 rec = __ldg(&edges[e]);
            int sidx = __float_as_int(rec.x);
            s += h[(size_t)sidx * DIM + j] * rec.y;
        }
    }
#pragma unroll
    for (int r = REP >> 1; r > 0; r >>= 1)
        s += __shfl_sync(0xffffffffu, s, lane + r * DIM);

    if (rep == 0) {
        float di = dinv[warp];
        agg[(size_t)warp * DIM + j] = s + h[(size_t)warp * DIM + j] * di * di;
    }
}

// ---------------- transform: out = relu(agg @ W + b) ----------------
template <int IN, int OUT>
__global__ void transform_kernel(const float* __restrict__ agg,
                                 const float* __restrict__ W,
                                 const float* __restrict__ b,
                                 float* __restrict__ outh) {
    __shared__ float sW[IN * OUT];
    __shared__ float sb[OUT];
    for (int t = threadIdx.x; t < IN * OUT; t += blockDim.x) sW[t] = W[t];
    for (int t = threadIdx.x; t < OUT; t += blockDim.x) sb[t] = b[t];
    __syncthreads();
    int i = blockIdx.x * blockDim.x + threadIdx.x;
    if (i >= N_NODES) return;
    float in[IN];
#pragma unroll
    for (int k = 0; k < IN; k++) in[k] = agg[(size_t)i * IN + k];
#pragma unroll
    for (int o = 0; o < OUT; o++) {
        float v = sb[o];
#pragma unroll
        for (int k = 0; k < IN; k++) v += in[k] * sW[k * OUT + o];
        outh[(size_t)i * OUT + o] = fmaxf(v, 0.0f);      // post-ReLU storage
    }
}

// ---------------- node projections for edge MLP ----------------
__global__ void node_proj_kernel(const float* __restrict__ h,
                                 const float* __restrict__ Wl1,
                                 float4* __restrict__ pa,
                                 float4* __restrict__ pb) {
    __shared__ float sW[64 * 4];
    for (int t = threadIdx.x; t < 64 * 4; t += blockDim.x) sW[t] = Wl1[t];
    __syncthreads();
    int i = blockIdx.x * blockDim.x + threadIdx.x;
    if (i >= N_NODES) return;
    float va[4] = {0, 0, 0, 0}, vb[4] = {0, 0, 0, 0};
#pragma unroll
    for (int k = 0; k < 32; k++) {
        float v = h[(size_t)i * 32 + k];                 // already relu'd
#pragma unroll
        for (int j = 0; j < 4; j++) {
            va[j] += v * sW[k * 4 + j];
            vb[j] += v * sW[(32 + k) * 4 + j];
        }
    }
    pa[i] = make_float4(va[0], va[1], va[2], va[3]);
    pb[i] = make_float4(vb[0], vb[1], vb[2], vb[3]);
}

// ---------------- final edge MLP: out = (pa[a]+pb[b]+bl1) @ Wl2 + bl2 ----------------
__global__ void edge_mlp_kernel(const int* __restrict__ w2b,
                                const float* __restrict__ bl1,
                                const float* __restrict__ Wl2,
                                const float* __restrict__ bl2,
                                const float4* __restrict__ pa,
                                const float4* __restrict__ pb,
                                float* __restrict__ out) {
    __shared__ float sW2[12], sb1[4], sb2[3];
    if (threadIdx.x < 12) sW2[threadIdx.x] = Wl2[threadIdx.x];
    if (threadIdx.x < 4)  sb1[threadIdx.x] = bl1[threadIdx.x];
    if (threadIdx.x < 3)  sb2[threadIdx.x] = bl2[threadIdx.x];
    __syncthreads();

    int e = blockIdx.x * blockDim.x + threadIdx.x;
    if (e >= N_W2B) return;
    int a = w2b[e];
    int b = w2b[e + N_W2B];
    float4 va = pa[a];
    float4 vb = pb[b];
    float h0 = va.x + vb.x + sb1[0];
    float h1 = va.y + vb.y + sb1[1];
    float h2 = va.z + vb.z + sb1[2];
    float h3 = va.w + vb.w + sb1[3];
#pragma unroll
    for (int c = 0; c < 3; c++) {
        out[(size_t)e * 3 + c] =
            h0 * sW2[0 * 3 + c] + h1 * sW2[1 * 3 + c] +
            h2 * sW2[2 * 3 + c] + h3 * sW2[3 * 3 + c] + sb2[c];
    }
}

// ---------------- launch ----------------
extern "C" void kernel_launch(void* const* d_in, const int* in_sizes, int n_in,
                              void* d_out, int out_size) {
    const float* x    = (const float*)d_in[0];
    const int*   eidx = (const int*)d_in[1];
    const int*   w2b  = (const int*)d_in[2];
    const float* ew   = (const float*)d_in[3];
    const float *W1 = (const float*)d_in[4],  *b1 = (const float*)d_in[5];
    const float *W2 = (const float*)d_in[6],  *b2 = (const float*)d_in[7];
    const float *W3 = (const float*)d_in[8],  *b3 = (const float*)d_in[9];
    const float *Wl1 = (const float*)d_in[10], *bl1 = (const float*)d_in[11];
    const float *Wl2 = (const float*)d_in[12], *bl2 = (const float*)d_in[13];
    float* out = (float*)d_out;

    float *dinv, *agg, *h1, *h2, *h3;
    int *cnt, *rowptr, *cursor, *bsums;
    float2 *edges;
    float4 *pa, *pb;
    cudaGetSymbolAddress((void**)&dinv,   g_dinv);
    cudaGetSymbolAddress((void**)&cnt,    g_cnt);
    cudaGetSymbolAddress((void**)&rowptr, g_rowptr);
    cudaGetSymbolAddress((void**)&cursor, g_cursor);
    cudaGetSymbolAddress((void**)&bsums,  g_bsums);
    cudaGetSymbolAddress((void**)&edges,  g_edges);
    cudaGetSymbolAddress((void**)&agg,    g_agg);
    cudaGetSymbolAddress((void**)&h1,     g_h1);
    cudaGetSymbolAddress((void**)&h2,     g_h2);
    cudaGetSymbolAddress((void**)&h3,     g_h3);
    cudaGetSymbolAddress((void**)&pa,     g_pa);
    cudaGetSymbolAddress((void**)&pb,     g_pb);

    const int* src = eidx;
    const int* dst = eidx + N_EDGES;

    const int T = 256;
    const int nb_nodes = (N_NODES + T - 1) / T;
    const int nb_edges = (N_EDGES + T - 1) / T;
    const int nb_w2b   = (N_W2B + T - 1) / T;
    const int nb_warp  = (N_NODES * 32 + T - 1) / T;   // one warp per node

    // stage 0: degree + histogram, dinv
    zero_kernel<<<nb_nodes, T>>>(dinv, cnt);
    pass1_kernel<<<nb_edges, T>>>(dst, ew, dinv, cnt);
    finalize_dinv_kernel<<<nb_nodes, T>>>(dinv);

    // scan cnt -> rowptr (exclusive) + cursor copy
    scan_block_kernel<<<N_SCANBLK, SCAN_B>>>(cnt, rowptr, bsums);
    scan_bsums_kernel<<<1, SCAN_B>>>(bsums);
    scan_add_kernel<<<N_SCANBLK, SCAN_B>>>(rowptr, cursor, bsums);

    // CSR fill (packed src+norm per slot)
    fill_kernel<<<nb_edges, T>>>(src, dst, ew, dinv, cursor, edges);

    // layer 1: aggregate x(7), transform 7->8
    aggregate_kernel<7><<<nb_warp, T>>>(rowptr, edges, x, dinv, agg);
    transform_kernel<7, 8><<<nb_nodes, T>>>(agg, W1, b1, h1);

    // layer 2: aggregate h1(8), transform 8->16
    aggregate_kernel<8><<<nb_warp, T>>>(rowptr, edges, h1, dinv, agg);
    transform_kernel<8, 16><<<nb_nodes, T>>>(agg, W2, b2, h2);

    // layer 3: aggregate h2(16), transform 16->32
    aggregate_kernel<16><<<nb_warp, T>>>(rowptr, edges, h2, dinv, agg);
    transform_kernel<16, 32><<<nb_nodes, T>>>(agg, W3, b3, h3);

    // edge MLP: per-node projection then 2M-edge combine
    node_proj_kernel<<<nb_nodes, T>>>(h3, Wl1, pa, pb);
    edge_mlp_kernel<<<nb_w2b, T>>>(w2b, bl1, Wl2, bl2, pa, pb, out);
}

// round 6
// speedup vs baseline: 4.8178x; 1.0491x over previous
#include <cuda_runtime.h>
#include <math.h>

// ---------------- problem constants ----------------
constexpr int N_NODES = 200000;
constexpr int N_EDGES = 4000000;
constexpr int N_W2B   = 2000000;
constexpr int SCAN_B  = 1024;
constexpr int N_SCANBLK = (N_NODES + SCAN_B - 1) / SCAN_B;   // 196

// ---------------- device scratch (static; no runtime allocs) ----------------
__device__ __align__(16) float  g_dinv[N_NODES];
__device__ __align__(16) int    g_cnt [N_NODES];
__device__ __align__(16) int    g_rowptr[N_NODES + 1];
__device__ __align__(16) int    g_cursor[N_NODES];
__device__ __align__(16) int    g_bsums[N_SCANBLK];
__device__ __align__(16) float2 g_edges[N_EDGES];          // packed (src, norm)
__device__ __align__(16) float  g_x8  [N_NODES * 8];       // padded input
__device__ __align__(16) float  g_h1  [N_NODES * 8];
__device__ __align__(16) float  g_h2  [N_NODES * 16];
__device__ __align__(16) float4 g_pa[N_NODES];
__device__ __align__(16) float4 g_pb[N_NODES];

__device__ __forceinline__ float sigmoidf_(float x) {
    return 1.0f / (1.0f + expf(-x));
}

// ---------------- stage 0: degree + histogram ----------------
__global__ void zero_kernel(float* deg, int* cnt) {
    int i = blockIdx.x * blockDim.x + threadIdx.x;
    if (i < N_NODES) { deg[i] = 0.0f; cnt[i] = 0; }
}

__global__ void pass1_kernel(const int* __restrict__ dst,
                             const float* __restrict__ ew,
                             float* deg, int* cnt) {
    int e = blockIdx.x * blockDim.x + threadIdx.x;
    if (e < N_EDGES) {
        int d = dst[e];
        atomicAdd(deg + d, sigmoidf_(ew[e]));
        atomicAdd(cnt + d, 1);
    }
}

// ---------------- exclusive scan of cnt -> rowptr ----------------
__global__ void scan_block_kernel(const int* __restrict__ cnt,
                                  int* __restrict__ excl,
                                  int* __restrict__ bsums) {
    __shared__ int sh[SCAN_B];
    int t = threadIdx.x;
    int gid = blockIdx.x * SCAN_B + t;
    int v = (gid < N_NODES) ? cnt[gid] : 0;
    sh[t] = v;
    __syncthreads();
#pragma unroll
    for (int off = 1; off < SCAN_B; off <<= 1) {
        int add = (t >= off) ? sh[t - off] : 0;
        __syncthreads();
        sh[t] += add;
        __syncthreads();
    }
    if (gid < N_NODES) excl[gid] = sh[t] - v;            // exclusive
    if (t == SCAN_B - 1) bsums[blockIdx.x] = sh[t];      // block total
}

__global__ void scan_bsums_kernel(int* bsums) {
    __shared__ int sh[N_SCANBLK];
    int t = threadIdx.x;
    if (t < N_SCANBLK) sh[t] = bsums[t];
    __syncthreads();
    if (t == 0) {
        int run = 0;
        for (int i = 0; i < N_SCANBLK; i++) { int c = sh[i]; sh[i] = run; run += c; }
    }
    __syncthreads();
    if (t < N_SCANBLK) bsums[t] = sh[t];
}

// also finalizes dinv (deg complete after pass1)
__global__ void scan_add_kernel(int* __restrict__ rowptr,
                                int* __restrict__ cursor,
                                const int* __restrict__ bsums,
                                float* dinv) {
    int gid = blockIdx.x * SCAN_B + threadIdx.x;
    if (gid < N_NODES) {
        int v = rowptr[gid] + bsums[blockIdx.x];
        rowptr[gid] = v;
        cursor[gid] = v;
        dinv[gid] = rsqrtf(dinv[gid] + 1.0f);            // +1: self-loop
        if (gid == 0) rowptr[N_NODES] = N_EDGES;
    }
}

// ---------------- CSR fill: one packed 8B record per edge ----------------
__global__ void fill_kernel(const int* __restrict__ src,
                            const int* __restrict__ dst,
                            const float* __restrict__ ew,
                            const float* __restrict__ dinv,
                            int* cursor,
                            float2* __restrict__ edges) {
    int e = blockIdx.x * blockDim.x + threadIdx.x;
    if (e >= N_EDGES) return;
    int s = src[e], d = dst[e];
    int pos = atomicAdd(cursor + d, 1);
    float nm = dinv[s] * sigmoidf_(ew[e]) * dinv[d];
    edges[pos] = make_float2(__int_as_float(s), nm);
}

// ---------------- pad x [N,7] -> x8 [N,8] ----------------
__global__ void pad_x_kernel(const float* __restrict__ x, float* __restrict__ x8) {
    int t = blockIdx.x * blockDim.x + threadIdx.x;
    if (t < N_NODES * 8) {
        int i = t >> 3, k = t & 7;
        x8[t] = (k < 7) ? x[i * 7 + k] : 0.0f;
    }
}

// ---------------- fused layer: gather + self-loop + GEMM + ReLU (+ final proj)
// one warp per node. Gather dim = DIM (lane = rep*DIM + j), transform IN->OUT.
template <int DIM, int IN, int OUT, bool FINAL>
__global__ void layer_kernel(const int* __restrict__ rowptr,
                             const float2* __restrict__ edges,
                             const float* __restrict__ h,
                             const float* __restrict__ dinv,
                             const float* __restrict__ W,
                             const float* __restrict__ b,
                             float* __restrict__ outh,
                             const float* __restrict__ Wl1,
                             float4* __restrict__ pa,
                             float4* __restrict__ pb) {
    constexpr int REP = 32 / DIM;
    __shared__ float sW[IN * OUT];
    for (int t = threadIdx.x; t < IN * OUT; t += blockDim.x) sW[t] = W[t];
    __syncthreads();

    int warp = (blockIdx.x * blockDim.x + threadIdx.x) >> 5;
    if (warp >= N_NODES) return;
    int lane = threadIdx.x & 31;
    int rep  = lane / DIM;
    int j    = lane - rep * DIM;

    int start = rowptr[warp];
    int end   = rowptr[warp + 1];

    float s = 0.0f;
    for (int e = start + rep; e < end; e += REP) {
        float2 rec = __ldg(&edges[e]);
        int sidx = __float_as_int(rec.x);
        s += h[(size_t)sidx * DIM + j] * rec.y;
    }
#pragma unroll
    for (int r = REP >> 1; r > 0; r >>= 1)
        s += __shfl_sync(0xffffffffu, s, lane + r * DIM);

    // add self-loop on the lanes that hold the reduced aggregate
    if (lane < DIM) {
        float di = dinv[warp];
        s += h[(size_t)warp * DIM + lane] * di * di;
    }

    // in-warp transform: lane o = output channel
    float v = __ldg(b + (lane & (OUT - 1)));
#pragma unroll
    for (int k = 0; k < IN; k++) {
        float ak = __shfl_sync(0xffffffffu, s, k);
        v += ak * sW[k * OUT + (lane & (OUT - 1))];
    }
    v = fmaxf(v, 0.0f);

    if (!FINAL) {
        if (lane < OUT) outh[(size_t)warp * OUT + lane] = v;
    } else {
        // OUT == 32: project v (channel=lane) through Wl1 -> pa(4), pb(4)
        float4 wa = __ldg((const float4*)Wl1 + lane);        // Wl1[lane][0..3]
        float4 wb = __ldg((const float4*)Wl1 + 32 + lane);   // Wl1[32+lane][0..3]
        float p[8] = {v * wa.x, v * wa.y, v * wa.z, v * wa.w,
                      v * wb.x, v * wb.y, v * wb.z, v * wb.w};
#pragma unroll
        for (int off = 16; off > 0; off >>= 1) {
#pragma unroll
            for (int q = 0; q < 8; q++)
                p[q] += __shfl_xor_sync(0xffffffffu, p[q], off);
        }
        if (lane == 0) {
            pa[warp] = make_float4(p[0], p[1], p[2], p[3]);
            pb[warp] = make_float4(p[4], p[5], p[6], p[7]);
        }
    }
}

// ---------------- final edge MLP: out = (pa[a]+pb[b]+bl1) @ Wl2 + bl2 ----------------
__global__ void edge_mlp_kernel(const int* __restrict__ w2b,
                                const float* __restrict__ bl1,
                                const float* __restrict__ Wl2,
                                const float* __restrict__ bl2,
                                const float4* __restrict__ pa,
                                const float4* __restrict__ pb,
                                float* __restrict__ out) {
    __shared__ float sW2[12], sb1[4], sb2[3];
    if (threadIdx.x < 12) sW2[threadIdx.x] = Wl2[threadIdx.x];
    if (threadIdx.x < 4)  sb1[threadIdx.x] = bl1[threadIdx.x];
    if (threadIdx.x < 3)  sb2[threadIdx.x] = bl2[threadIdx.x];
    __syncthreads();

    int e = blockIdx.x * blockDim.x + threadIdx.x;
    if (e >= N_W2B) return;
    int a = w2b[e];
    int b = w2b[e + N_W2B];
    float4 va = __ldg(pa + a);
    float4 vb = __ldg(pb + b);
    float h0 = va.x + vb.x + sb1[0];
    float h1 = va.y + vb.y + sb1[1];
    float h2 = va.z + vb.z + sb1[2];
    float h3 = va.w + vb.w + sb1[3];
#pragma unroll
    for (int c = 0; c < 3; c++) {
        out[(size_t)e * 3 + c] =
            h0 * sW2[0 * 3 + c] + h1 * sW2[1 * 3 + c] +
            h2 * sW2[2 * 3 + c] + h3 * sW2[3 * 3 + c] + sb2[c];
    }
}

// ---------------- launch ----------------
extern "C" void kernel_launch(void* const* d_in, const int* in_sizes, int n_in,
                              void* d_out, int out_size) {
    const float* x    = (const float*)d_in[0];
    const int*   eidx = (const int*)d_in[1];
    const int*   w2b  = (const int*)d_in[2];
    const float* ew   = (const float*)d_in[3];
    const float *W1 = (const float*)d_in[4],  *b1 = (const float*)d_in[5];
    const float *W2 = (const float*)d_in[6],  *b2 = (const float*)d_in[7];
    const float *W3 = (const float*)d_in[8],  *b3 = (const float*)d_in[9];
    const float *Wl1 = (const float*)d_in[10], *bl1 = (const float*)d_in[11];
    const float *Wl2 = (const float*)d_in[12], *bl2 = (const float*)d_in[13];
    float* out = (float*)d_out;

    float *dinv, *x8, *h1, *h2;
    int *cnt, *rowptr, *cursor, *bsums;
    float2 *edges;
    float4 *pa, *pb;
    cudaGetSymbolAddress((void**)&dinv,   g_dinv);
    cudaGetSymbolAddress((void**)&cnt,    g_cnt);
    cudaGetSymbolAddress((void**)&rowptr, g_rowptr);
    cudaGetSymbolAddress((void**)&cursor, g_cursor);
    cudaGetSymbolAddress((void**)&bsums,  g_bsums);
    cudaGetSymbolAddress((void**)&edges,  g_edges);
    cudaGetSymbolAddress((void**)&x8,     g_x8);
    cudaGetSymbolAddress((void**)&h1,     g_h1);
    cudaGetSymbolAddress((void**)&h2,     g_h2);
    cudaGetSymbolAddress((void**)&pa,     g_pa);
    cudaGetSymbolAddress((void**)&pb,     g_pb);

    const int* src = eidx;
    const int* dst = eidx + N_EDGES;

    const int T = 256;
    const int nb_nodes = (N_NODES + T - 1) / T;
    const int nb_edges = (N_EDGES + T - 1) / T;
    const int nb_w2b   = (N_W2B + T - 1) / T;
    const int nb_warp  = (N_NODES * 32 + T - 1) / T;   // one warp per node
    const int nb_pad   = (N_NODES * 8 + T - 1) / T;

    // stage 0: degree + histogram
    zero_kernel<<<nb_nodes, T>>>(dinv, cnt);
    pass1_kernel<<<nb_edges, T>>>(dst, ew, dinv, cnt);

    // scan cnt -> rowptr (exclusive) + cursor copy + dinv finalize
    scan_block_kernel<<<N_SCANBLK, SCAN_B>>>(cnt, rowptr, bsums);
    scan_bsums_kernel<<<1, SCAN_B>>>(bsums);
    scan_add_kernel<<<N_SCANBLK, SCAN_B>>>(rowptr, cursor, bsums, dinv);

    // CSR fill (packed src+norm per slot) + pad x
    fill_kernel<<<nb_edges, T>>>(src, dst, ew, dinv, cursor, edges);
    pad_x_kernel<<<nb_pad, T>>>(x, x8);

    // fused layers
    layer_kernel<8, 7, 8, false><<<nb_warp, T>>>(rowptr, edges, x8, dinv, W1, b1, h1, nullptr, nullptr, nullptr);
    layer_kernel<8, 8, 16, false><<<nb_warp, T>>>(rowptr, edges, h1, dinv, W2, b2, h2, nullptr, nullptr, nullptr);
    layer_kernel<16, 16, 32, true><<<nb_warp, T>>>(rowptr, edges, h2, dinv, W3, b3, nullptr, Wl1, pa, pb);

    // 2M-edge combine
    edge_mlp_kernel<<<nb_w2b, T>>>(w2b, bl1, Wl2, bl2, pa, pb, out);
}